// round 1
// baseline (speedup 1.0000x reference)
#include <cuda_runtime.h>
#include <cstdint>

typedef unsigned long long ull;

// ---- packed f32x2 helpers (sm_100+ PTX) ----
__device__ __forceinline__ ull fma2(ull a, ull b, ull c) {
    ull d;
    asm("fma.rn.f32x2 %0, %1, %2, %3;" : "=l"(d) : "l"(a), "l"(b), "l"(c));
    return d;
}
__device__ __forceinline__ ull pk(float a, float b) {
    ull r; asm("mov.b64 %0, {%1, %2};" : "=l"(r) : "f"(a), "f"(b)); return r;
}
__device__ __forceinline__ float2 unpk(ull v) {
    float2 r; asm("mov.b64 {%0, %1}, %2;" : "=f"(r.x), "=f"(r.y) : "l"(v)); return r;
}

#define TZ 128          // z rows per tile
#define FSTRIDE 132     // floats per k-row in feature smem (pad vs 128 for banks)
#define NTHREADS 256

// C[128z x 128w] += f(K=128,z) * W(K=128,w); thread microtile 8z x 8w,
// accumulators are f32x2 pairs over adjacent z.
__device__ __forceinline__ void gemm128(const float* __restrict__ fsm,
                                        const float* __restrict__ wsm,
                                        int tx, int ty, ull acc[4][8]) {
    const float4* f4 = reinterpret_cast<const float4*>(fsm);
    const float4* w4 = reinterpret_cast<const float4*>(wsm);
#pragma unroll 4
    for (int k = 0; k < 128; ++k) {
        float4 fa = f4[k * (FSTRIDE / 4) + 2 * ty];
        float4 fb = f4[k * (FSTRIDE / 4) + 2 * ty + 1];
        float4 wa = w4[k * 32 + 2 * tx];
        float4 wb = w4[k * 32 + 2 * tx + 1];
        ull f0 = pk(fa.x, fa.y), f1 = pk(fa.z, fa.w);
        ull f2 = pk(fb.x, fb.y), f3 = pk(fb.z, fb.w);
        float wv[8] = {wa.x, wa.y, wa.z, wa.w, wb.x, wb.y, wb.z, wb.w};
#pragma unroll
        for (int j = 0; j < 8; ++j) {
            ull wd = pk(wv[j], wv[j]);
            acc[0][j] = fma2(f0, wd, acc[0][j]);
            acc[1][j] = fma2(f1, wd, acc[1][j]);
            acc[2][j] = fma2(f2, wd, acc[2][j]);
            acc[3][j] = fma2(f3, wd, acc[3][j]);
        }
    }
}

__global__ void __launch_bounds__(NTHREADS, 1)
tp_kernel(const float* __restrict__ x1, const float* __restrict__ x2,
          const float* __restrict__ wts, float* __restrict__ out,
          int Z, int NA, int NB) {
    extern __shared__ float sm[];
    float* Wsm = sm;                   // 32768 floats: two 128x128 weight halves
    float* fsm = sm + 32768;           // 128 * 132 floats: features / out-stage
    float* x2s = sm + 32768 + 16896;   // 128 * 4 floats
    const int tid = threadIdx.x;
    const int tx = tid & 15, ty = tid >> 4;
    const bool roleA = (int)blockIdx.x < NA;

    // role A: [W0 ; W3]  (out0 path)   role B: [W1 ; W2]  (out1 path)
    const float* s0 = roleA ? wts : (wts + 16384);
    const float* s1 = roleA ? (wts + 49152) : (wts + 32768);
    {
        const float4* a4 = (const float4*)s0;
        const float4* b4 = (const float4*)s1;
        float4* W4 = (float4*)Wsm;
        for (int i = tid; i < 4096; i += NTHREADS) {
            W4[i] = a4[i];
            W4[4096 + i] = b4[i];
        }
    }

    const int NT = (Z + TZ - 1) / TZ;
    const int b = roleA ? (int)blockIdx.x : ((int)blockIdx.x - NA);
    const int nb = roleA ? NA : NB;
    const float inv16 = 0.0625f;
    const float c2 = 0.03608439182435161f;  // 1/(16*sqrt(3))

    for (int t = b; t < NT; t += nb) {
        const int z0 = t * TZ;
        const int zv = min(TZ, Z - z0);
        __syncthreads();  // protect fsm/x2s from previous iteration readers
        for (int i = tid; i < TZ * 4; i += NTHREADS) {
            int z = i >> 2;
            x2s[i] = (z < zv) ? x2[(z0 + z) * 4 + (i & 3)] : 0.0f;
        }
        __syncthreads();

        if (roleA) {
            // phase A1 features: f[u][z] = s*a_u/16
            for (int i = tid; i < 128 * TZ; i += NTHREADS) {
                int z = i >> 7, u = i & 127;
                float v = 0.0f;
                if (z < zv) v = inv16 * x2s[z * 4] * x1[(size_t)(z0 + z) * 512 + u];
                fsm[u * FSTRIDE + z] = v;
            }
            __syncthreads();
            ull acc[4][8];
#pragma unroll
            for (int i = 0; i < 4; ++i)
#pragma unroll
                for (int j = 0; j < 8; ++j) acc[i][j] = 0ULL;
            gemm128(fsm, Wsm, tx, ty, acc);
            __syncthreads();
            // phase A2 features: f[u][z] = (B_u . v)/(16*sqrt3)
            for (int i = tid; i < 128 * TZ; i += NTHREADS) {
                int z = i >> 7, u = i & 127;
                float v = 0.0f;
                if (z < zv) {
                    const float* Bp = x1 + (size_t)(z0 + z) * 512 + 128 + 3 * u;
                    v = c2 * (Bp[0] * x2s[z * 4 + 1] + Bp[1] * x2s[z * 4 + 2] +
                              Bp[2] * x2s[z * 4 + 3]);
                }
                fsm[u * FSTRIDE + z] = v;
            }
            __syncthreads();
            gemm128(fsm, Wsm + 128 * 128, tx, ty, acc);
            // epilogue: direct coalesced stores of out0
            const int zb = ty * 8;
#pragma unroll
            for (int i = 0; i < 4; ++i) {
                int zA = zb + 2 * i, zB = zA + 1;
                float2 p[8];
#pragma unroll
                for (int j = 0; j < 8; ++j) p[j] = unpk(acc[i][j]);
                if (zA < zv) {
                    float4* o = (float4*)(out + (size_t)(z0 + zA) * 512 + tx * 8);
                    o[0] = make_float4(p[0].x, p[1].x, p[2].x, p[3].x);
                    o[1] = make_float4(p[4].x, p[5].x, p[6].x, p[7].x);
                }
                if (zB < zv) {
                    float4* o = (float4*)(out + (size_t)(z0 + zB) * 512 + tx * 8);
                    o[0] = make_float4(p[0].y, p[1].y, p[2].y, p[3].y);
                    o[1] = make_float4(p[4].y, p[5].y, p[6].y, p[7].y);
                }
            }
        } else {
            // phase B0: t1 = (a/16) @ W1, kept in registers
            for (int i = tid; i < 128 * TZ; i += NTHREADS) {
                int z = i >> 7, u = i & 127;
                float v = 0.0f;
                if (z < zv) v = inv16 * x1[(size_t)(z0 + z) * 512 + u];
                fsm[u * FSTRIDE + z] = v;
            }
            __syncthreads();
            ull t1[4][8];
#pragma unroll
            for (int i = 0; i < 4; ++i)
#pragma unroll
                for (int j = 0; j < 8; ++j) t1[i][j] = 0ULL;
            gemm128(fsm, Wsm, tx, ty, t1);

            for (int kk = 0; kk < 3; ++kk) {
                __syncthreads();  // everyone done reading fsm
                // features: f[u][z] = s*B[u,kk]/16
                for (int i = tid; i < 128 * TZ; i += NTHREADS) {
                    int z = i >> 7, u = i & 127;
                    float v = 0.0f;
                    if (z < zv)
                        v = inv16 * x2s[z * 4] *
                            x1[(size_t)(z0 + z) * 512 + 128 + 3 * u + kk];
                    fsm[u * FSTRIDE + z] = v;
                }
                __syncthreads();
                ull up[4][8];
#pragma unroll
                for (int i = 0; i < 4; ++i)
#pragma unroll
                    for (int j = 0; j < 8; ++j) up[i][j] = 0ULL;
                gemm128(fsm, Wsm + 128 * 128, tx, ty, up);
                __syncthreads();  // done reading fsm -> reuse as out stage
                // combine v_k*t1 + u_k, stage to smem as [z][w]
                const int zb = ty * 8;
#pragma unroll
                for (int i = 0; i < 4; ++i) {
                    int zA = zb + 2 * i, zB = zA + 1;
                    float vA = x2s[zA * 4 + 1 + kk];
                    float vB = x2s[zB * 4 + 1 + kk];
                    float rA[8], rB[8];
#pragma unroll
                    for (int j = 0; j < 8; ++j) {
                        float2 tt = unpk(t1[i][j]);
                        float2 uu = unpk(up[i][j]);
                        rA[j] = fmaf(vA, tt.x, uu.x);
                        rB[j] = fmaf(vB, tt.y, uu.y);
                    }
                    *(float4*)&fsm[zA * FSTRIDE + tx * 8] =
                        make_float4(rA[0], rA[1], rA[2], rA[3]);
                    *(float4*)&fsm[zA * FSTRIDE + tx * 8 + 4] =
                        make_float4(rA[4], rA[5], rA[6], rA[7]);
                    *(float4*)&fsm[zB * FSTRIDE + tx * 8] =
                        make_float4(rB[0], rB[1], rB[2], rB[3]);
                    *(float4*)&fsm[zB * FSTRIDE + tx * 8 + 4] =
                        make_float4(rB[4], rB[5], rB[6], rB[7]);
                }
                __syncthreads();
                // cooperative store, stride-3 in gmem (L2 merges sectors)
                for (int i = tid; i < TZ * 128; i += NTHREADS) {
                    int z = i >> 7, ww = i & 127;
                    if (z < zv)
                        out[(size_t)(z0 + z) * 512 + 128 + 3 * ww + kk] =
                            fsm[z * FSTRIDE + ww];
                }
            }
        }
    }
}

extern "C" void kernel_launch(void* const* d_in, const int* in_sizes, int n_in,
                              void* d_out, int out_size) {
    const float* x1 = (const float*)d_in[0];
    const float* x2 = (const float*)d_in[1];
    const float* w  = (const float*)d_in[2];
    float* out = (float*)d_out;
    const int Z = in_sizes[0] / 512;

    int dev = 0;
    cudaGetDevice(&dev);
    int sms = 148;
    cudaDeviceGetAttribute(&sms, cudaDevAttrMultiProcessorCount, dev);

    const size_t SMEM = (32768 + 128 * FSTRIDE + 512) * sizeof(float);  // 200704 B
    cudaFuncSetAttribute(tp_kernel, cudaFuncAttributeMaxDynamicSharedMemorySize,
                         (int)SMEM);

    int grid = sms;
    int NA = (grid * 293 + 500) / 1000;  // ~29% of CTAs on the out0 role
    if (NA < 1) NA = 1;
    if (NA > grid - 1) NA = grid - 1;
    int NB = grid - NA;

    tp_kernel<<<grid, NTHREADS, SMEM>>>(x1, x2, w, out, Z, NA, NB);
}

// round 3
// speedup vs baseline: 1.8598x; 1.8598x over previous
#include <cuda_runtime.h>
#include <cuda_fp16.h>
#include <cstdint>

#define NTH 256
#define TZ 128

// ---- smem byte offsets (all fp16 matrices stored [row][k], 128 cols, 256B/row, swizzled) ----
#define OFF_W0 0         // out0 path, slot-a features
#define OFF_W3 32768     // out0 path, q features
#define OFF_W1 65536     // t1 = a @ W1
#define OFF_W2 98304     // u_k = s*b_k @ W2
#define OFF_F  131072    // feature tile [z][u] fp16, 32 KB
#define OFF_X2 163840    // 128*4 floats
#define SMEM_BYTES (163840 + 2048)

static __device__ __forceinline__ uint32_t s2u(const void* p) {
    uint32_t a;
    asm("{ .reg .u64 t; cvta.to.shared.u64 t, %1; cvt.u32.u64 %0, t; }"
        : "=r"(a) : "l"(p));
    return a;
}

static __device__ __forceinline__ uint32_t pkh2(float a, float b) {
    __half2 h = __floats2half2_rn(a, b);   // x=a (low), y=b (high)
    return *reinterpret_cast<uint32_t*>(&h);
}

static __device__ __forceinline__ void ldsm4(uint32_t addr, uint32_t r[4]) {
    asm volatile("ldmatrix.sync.aligned.m8n8.x4.shared.b16 {%0,%1,%2,%3}, [%4];"
                 : "=r"(r[0]), "=r"(r[1]), "=r"(r[2]), "=r"(r[3])
                 : "r"(addr));
}

static __device__ __forceinline__ void mma16816(float d[4], const uint32_t a[4],
                                                uint32_t b0, uint32_t b1) {
    asm volatile(
        "mma.sync.aligned.m16n8k16.row.col.f32.f16.f16.f32 "
        "{%0,%1,%2,%3}, {%4,%5,%6,%7}, {%8,%9}, {%0,%1,%2,%3};"
        : "+f"(d[0]), "+f"(d[1]), "+f"(d[2]), "+f"(d[3])
        : "r"(a[0]), "r"(a[1]), "r"(a[2]), "r"(a[3]), "r"(b0), "r"(b1));
}

// one 128x128x128 GEMM: D[z,w] += F[z,:] @ W[w,:]^T
// warp (wm,wn): z rows [32*wm, 32*wm+32), w cols [64*wn, 64*wn+64)
static __device__ __forceinline__ void gemm_round(uint32_t sb, uint32_t woff,
                                                  int wm, int wn, int lane,
                                                  float d[2][8][4]) {
    const uint32_t fbase = sb + OFF_F;
    const uint32_t wbase = sb + woff;
    const int arow0 = 32 * wm + (lane & 15);
    const int achunkh = lane >> 4;
    const int brow0 = 64 * wn + ((lane >> 4) << 3) + (lane & 7);
    const int bchunkh = (lane >> 3) & 1;
#pragma unroll
    for (int ks = 0; ks < 8; ++ks) {
        uint32_t a[2][4];
#pragma unroll
        for (int mt = 0; mt < 2; ++mt) {
            int row = arow0 + 16 * mt;
            int chunk = ks * 2 + achunkh;
            ldsm4(fbase + row * 256 + ((chunk ^ (row & 7)) << 4), a[mt]);
        }
        uint32_t b[4][4];
#pragma unroll
        for (int nb = 0; nb < 4; ++nb) {
            int row = brow0 + 16 * nb;
            int chunk = ks * 2 + bchunkh;
            ldsm4(wbase + row * 256 + ((chunk ^ (row & 7)) << 4), b[nb]);
        }
#pragma unroll
        for (int mt = 0; mt < 2; ++mt)
#pragma unroll
            for (int nt = 0; nt < 8; ++nt)
                mma16816(d[mt][nt], a[mt], b[nt >> 1][(nt & 1) * 2],
                         b[nt >> 1][(nt & 1) * 2 + 1]);
    }
}

__global__ void __launch_bounds__(NTH, 1)
tp_hmma(const float* __restrict__ x1, const float* __restrict__ x2,
        const float* __restrict__ wts, float* __restrict__ out, int Z, int NT) {
    extern __shared__ char smc[];
    const uint32_t sb = s2u(smc);
    float* x2s = (float*)(smc + OFF_X2);
    const int tid = threadIdx.x;
    const int lane = tid & 31, wid = tid >> 5;
    const int wm = wid & 3, wn = wid >> 2;
    const float inv16 = 0.0625f;
    const float c2 = 0.03608439182435161f;  // 1/(16*sqrt(3))

    // ---- load + transpose + fp16-convert the 4 weight matrices into smem ----
    {
        const int srcoff[4] = {0, 49152, 16384, 32768};       // W0, W3, W1, W2
        const int dstoff[4] = {OFF_W0, OFF_W3, OFF_W1, OFF_W2};
#pragma unroll
        for (int m = 0; m < 4; ++m) {
            const float* src = wts + srcoff[m];   // layout [u][w]
            char* dst = smc + dstoff[m];          // layout [w][u] fp16 swizzled
            for (int i = tid; i < 2048; i += NTH) {
                int w = i >> 4, uc = i & 15;
                uint32_t h[4];
#pragma unroll
                for (int j = 0; j < 4; ++j) {
                    float f0 = src[(uc * 8 + 2 * j) * 128 + w];
                    float f1 = src[(uc * 8 + 2 * j + 1) * 128 + w];
                    h[j] = pkh2(f0, f1);
                }
                *(uint4*)(dst + w * 256 + ((uc ^ (w & 7)) << 4)) =
                    make_uint4(h[0], h[1], h[2], h[3]);
            }
        }
    }
    __syncthreads();

    for (int t = blockIdx.x; t < NT; t += gridDim.x) {
        const int z0t = t * TZ;
        const int zv = min(TZ, Z - z0t);
        __syncthreads();  // protect x2s/F from previous-iter readers
        for (int i = tid; i < TZ * 4; i += NTH) {
            int z = i >> 2;
            x2s[i] = (z < zv) ? x2[(size_t)(z0t + z) * 4 + (i & 3)] : 0.0f;
        }
        __syncthreads();

        // ======== out0 = (s*a/16) @ W0 + q @ W3 ========
        float d0[2][8][4];
#pragma unroll
        for (int mt = 0; mt < 2; ++mt)
#pragma unroll
            for (int nt = 0; nt < 8; ++nt)
#pragma unroll
                for (int r = 0; r < 4; ++r) d0[mt][nt][r] = 0.0f;

        // phase A: f = s*a/16
#pragma unroll
        for (int it = 0; it < 8; ++it) {
            int i = tid + it * NTH;
            int z = i >> 4, uc = i & 15;
            uint4 wv = make_uint4(0, 0, 0, 0);
            if (z < zv) {
                const float* row = x1 + (size_t)(z0t + z) * 512 + uc * 8;
                float s = inv16 * x2s[4 * z];
                float4 p0 = *(const float4*)(row);
                float4 p1 = *(const float4*)(row + 4);
                wv = make_uint4(pkh2(s * p0.x, s * p0.y), pkh2(s * p0.z, s * p0.w),
                                pkh2(s * p1.x, s * p1.y), pkh2(s * p1.z, s * p1.w));
            }
            *(uint4*)(smc + OFF_F + z * 256 + ((uc ^ (z & 7)) << 4)) = wv;
        }
        __syncthreads();
        gemm_round(sb, OFF_W0, wm, wn, lane, d0);
        __syncthreads();

        // phase B: f = (B_u . v) / (16*sqrt3)
#pragma unroll
        for (int it = 0; it < 8; ++it) {
            int i = tid + it * NTH;
            int z = i >> 4, uc = i & 15;
            uint4 wv = make_uint4(0, 0, 0, 0);
            if (z < zv) {
                const float* bp = x1 + (size_t)(z0t + z) * 512 + 128 + 24 * uc;
                float v1 = x2s[4 * z + 1], v2 = x2s[4 * z + 2], v3 = x2s[4 * z + 3];
                float arr[24];
#pragma unroll
                for (int q = 0; q < 6; ++q)
                    *(float4*)(arr + 4 * q) = *(const float4*)(bp + 4 * q);
                float f[8];
#pragma unroll
                for (int j = 0; j < 8; ++j)
                    f[j] = c2 * (arr[3 * j] * v1 + arr[3 * j + 1] * v2 +
                                 arr[3 * j + 2] * v3);
                wv = make_uint4(pkh2(f[0], f[1]), pkh2(f[2], f[3]),
                                pkh2(f[4], f[5]), pkh2(f[6], f[7]));
            }
            *(uint4*)(smc + OFF_F + z * 256 + ((uc ^ (z & 7)) << 4)) = wv;
        }
        __syncthreads();
        gemm_round(sb, OFF_W3, wm, wn, lane, d0);

        // store out0 (cols [64*wn, 64*wn+64))
#pragma unroll
        for (int mt = 0; mt < 2; ++mt) {
            int zl = 32 * wm + 16 * mt + (lane >> 2);
#pragma unroll
            for (int nt = 0; nt < 8; ++nt) {
                int c = 64 * wn + nt * 8 + (lane & 3) * 2;
                if (zl < zv)
                    *(float2*)(out + (size_t)(z0t + zl) * 512 + c) =
                        make_float2(d0[mt][nt][0], d0[mt][nt][1]);
                if (zl + 8 < zv)
                    *(float2*)(out + (size_t)(z0t + zl + 8) * 512 + c) =
                        make_float2(d0[mt][nt][2], d0[mt][nt][3]);
            }
        }
        __syncthreads();

        // ======== t1 = (a/16) @ W1 ========
#pragma unroll
        for (int it = 0; it < 8; ++it) {
            int i = tid + it * NTH;
            int z = i >> 4, uc = i & 15;
            uint4 wv = make_uint4(0, 0, 0, 0);
            if (z < zv) {
                const float* row = x1 + (size_t)(z0t + z) * 512 + uc * 8;
                float4 p0 = *(const float4*)(row);
                float4 p1 = *(const float4*)(row + 4);
                wv = make_uint4(pkh2(inv16 * p0.x, inv16 * p0.y),
                                pkh2(inv16 * p0.z, inv16 * p0.w),
                                pkh2(inv16 * p1.x, inv16 * p1.y),
                                pkh2(inv16 * p1.z, inv16 * p1.w));
            }
            *(uint4*)(smc + OFF_F + z * 256 + ((uc ^ (z & 7)) << 4)) = wv;
        }
        __syncthreads();
        float dt[2][8][4];
#pragma unroll
        for (int mt = 0; mt < 2; ++mt)
#pragma unroll
            for (int nt = 0; nt < 8; ++nt)
#pragma unroll
                for (int r = 0; r < 4; ++r) dt[mt][nt][r] = 0.0f;
        gemm_round(sb, OFF_W1, wm, wn, lane, dt);
        __syncthreads();

        // ======== for k: u_k = (s*b_k/16) @ W2 ; out1 = v_k*t1 + u_k ========
        for (int k = 0; k < 3; ++k) {
#pragma unroll
            for (int it = 0; it < 8; ++it) {
                int i = tid + it * NTH;
                int z = i >> 4, uc = i & 15;
                uint4 wv = make_uint4(0, 0, 0, 0);
                if (z < zv) {
                    const float* bp = x1 + (size_t)(z0t + z) * 512 + 128 + 24 * uc;
                    float s = inv16 * x2s[4 * z];
                    float arr[24];
#pragma unroll
                    for (int q = 0; q < 6; ++q)
                        *(float4*)(arr + 4 * q) = *(const float4*)(bp + 4 * q);
                    wv = make_uint4(pkh2(s * arr[k], s * arr[3 + k]),
                                    pkh2(s * arr[6 + k], s * arr[9 + k]),
                                    pkh2(s * arr[12 + k], s * arr[15 + k]),
                                    pkh2(s * arr[18 + k], s * arr[21 + k]));
                }
                *(uint4*)(smc + OFF_F + z * 256 + ((uc ^ (z & 7)) << 4)) = wv;
            }
            __syncthreads();
            float du[2][8][4];
#pragma unroll
            for (int mt = 0; mt < 2; ++mt)
#pragma unroll
                for (int nt = 0; nt < 8; ++nt)
#pragma unroll
                    for (int r = 0; r < 4; ++r) du[mt][nt][r] = 0.0f;
            gemm_round(sb, OFF_W2, wm, wn, lane, du);

            // combine + store out1[:, w, k] at column 128 + 3w + k
#pragma unroll
            for (int mt = 0; mt < 2; ++mt) {
                int zl = 32 * wm + 16 * mt + (lane >> 2);
                float vA = x2s[4 * zl + 1 + k];
                float vB = x2s[4 * (zl + 8) + 1 + k];
#pragma unroll
                for (int nt = 0; nt < 8; ++nt) {
                    int c = 64 * wn + nt * 8 + (lane & 3) * 2;
                    if (zl < zv) {
                        float* o = out + (size_t)(z0t + zl) * 512 + 128 + k;
                        o[3 * c] = fmaf(vA, dt[mt][nt][0], du[mt][nt][0]);
                        o[3 * (c + 1)] = fmaf(vA, dt[mt][nt][1], du[mt][nt][1]);
                    }
                    if (zl + 8 < zv) {
                        float* o = out + (size_t)(z0t + zl + 8) * 512 + 128 + k;
                        o[3 * c] = fmaf(vB, dt[mt][nt][2], du[mt][nt][2]);
                        o[3 * (c + 1)] = fmaf(vB, dt[mt][nt][3], du[mt][nt][3]);
                    }
                }
            }
            __syncthreads();
        }
    }
}

extern "C" void kernel_launch(void* const* d_in, const int* in_sizes, int n_in,
                              void* d_out, int out_size) {
    const float* x1 = (const float*)d_in[0];
    const float* x2 = (const float*)d_in[1];
    const float* w = (const float*)d_in[2];
    float* out = (float*)d_out;
    const int Z = in_sizes[0] / 512;
    const int NT = (Z + TZ - 1) / TZ;

    int dev = 0;
    cudaGetDevice(&dev);
    int sms = 148;
    cudaDeviceGetAttribute(&sms, cudaDevAttrMultiProcessorCount, dev);

    cudaFuncSetAttribute(tp_hmma, cudaFuncAttributeMaxDynamicSharedMemorySize,
                         SMEM_BYTES);
    int grid = sms < NT ? sms : NT;
    tp_hmma<<<grid, NTH, SMEM_BYTES>>>(x1, x2, w, out, Z, NT);
}